// round 9
// baseline (speedup 1.0000x reference)
#include <cuda_runtime.h>
#include <math.h>

#define NB 32
#define NT 512
#define NE 300
#define NH 512
#define NG 2048   // 4*NH

#define NCTA_B 128
#define THR_B  512
#define GRPS   4          // independent batch groups
#define GB     8          // batches per group
#define CPG    32         // CTAs per group
#define JB     16         // j-columns per CTA

#define US2S   34         // u64 per U row (32 used; EVEN -> 16B-aligned pairs)
#define REDB   68         // red floats per (kt,b) row (64 used)

typedef unsigned long long u64;

// ---------------------------------------------------------------------------
__device__ __forceinline__ u64 pack2(float lo, float hi) {
    u64 r; asm("mov.b64 %0, {%1,%2};" : "=l"(r) : "f"(lo), "f"(hi)); return r;
}
__device__ __forceinline__ void fma2(u64& d, u64 a, u64 b) {
    asm("fma.rn.f32x2 %0, %1, %2, %0;" : "+l"(d) : "l"(a), "l"(b));
}
__device__ __forceinline__ float2 unpack2(u64 v) {
    float2 f; asm("mov.b64 {%0,%1}, %2;" : "=f"(f.x), "=f"(f.y) : "l"(v)); return f;
}

__device__ __forceinline__ float fast_sig(float x) {
    float e = __expf(-x);
    return __fdividef(1.f, 1.f + e);
}
__device__ __forceinline__ float fast_tanh(float x) {
    float e = __expf(2.f * x);
    return 1.f - 2.f * __fdividef(1.f, e + 1.f);
}

__device__ __forceinline__ void rel_add(unsigned int* p) {
    asm volatile("red.release.gpu.global.add.u32 [%0], %1;"
                 :: "l"(p), "r"(1u) : "memory");
}
__device__ __forceinline__ unsigned int acq_ld(unsigned int* p) {
    unsigned int v;
    asm volatile("ld.acquire.gpu.global.u32 %0, [%1];"
                 : "=r"(v) : "l"(p) : "memory");
    return v;
}

// Scratch (device globals)
// xz layout: [t][j][b][gate]  (one float4 per (t,j,b))
__device__ float g_xz[(size_t)NT * NH * NB * 4];
// h ring: 4 slots; slot s holds h[t] with t == s (mod 4). [slot][group][j*8+b]
__device__ float g_h[4][GRPS][NH * GB];
// per-CTA step flags (padded 128B apart): flag = # steps published
__device__ unsigned int g_flag[GRPS * CPG * 32];
// read-done counters per (slot, group), padded
__device__ unsigned int g_rd[4 * GRPS * 32];

// ---------------------------------------------------------------------------
// Kernel A: z[t][n][b] = sum_k emb[tok(b,t)][k] * W[k][n] + bias[n]
// Tiles 64(M)x64(N), BK=25, f32x2. Also zeroes g_h slot0 / flags / counters.
// ---------------------------------------------------------------------------
__global__ __launch_bounds__(256) void xz_kernel(
    const int* __restrict__ tokens, const float* __restrict__ emb,
    const float* __restrict__ W, const float* __restrict__ bias)
{
    __shared__ float As[25 * 68];
    __shared__ u64   Bs2[25 * 68];
    __shared__ int   toks[64];

    int tid = threadIdx.x;
    int m0 = blockIdx.y * 64;
    int n0 = blockIdx.x * 64;

    // init duty (stream-ordered before lstm kernel)
    if (blockIdx.x == 0 && blockIdx.y < 16) {       // zero h slot 0 (16K floats)
        int i = blockIdx.y * 256 + tid;             // 0..4095 float4
        ((float4*)g_h[0])[i] = make_float4(0.f, 0.f, 0.f, 0.f);
    }
    if (blockIdx.x == 1 && blockIdx.y < 16) {       // zero flags (4096 u32)
        int i = blockIdx.y * 256 + tid;
        g_flag[i] = 0u;
    }
    if (blockIdx.x == 2 && blockIdx.y < 2) {        // zero read counters (512 u32)
        int i = blockIdx.y * 256 + tid;
        g_rd[i] = 0u;
    }

    if (tid < 64) {
        int m = m0 + tid;
        toks[tid] = tokens[(m & 31) * NT + (m >> 5)];
    }
    __syncthreads();

    int tm = tid & 15, tn = tid >> 4;
    u64 acc2[2][4];
    #pragma unroll
    for (int p = 0; p < 2; ++p)
        #pragma unroll
        for (int j = 0; j < 4; ++j) acc2[p][j] = 0ull;

    for (int k0 = 0; k0 < NE; k0 += 25) {
        for (int idx = tid; idx < 64 * 25; idx += 256) {
            int m = idx / 25, kk = idx - m * 25;
            As[kk * 68 + m] = emb[(size_t)toks[m] * NE + k0 + kk];
        }
        for (int idx = tid; idx < 25 * 64; idx += 256) {
            int kk = idx >> 6, n = idx & 63;
            float w = W[(size_t)(k0 + kk) * NG + n0 + n];
            Bs2[kk * 68 + n] = pack2(w, w);
        }
        __syncthreads();

        #pragma unroll
        for (int kk = 0; kk < 25; ++kk) {
            float4 av = *(const float4*)&As[kk * 68 + tm * 4];
            ulonglong2 b01 = *(const ulonglong2*)&Bs2[kk * 68 + tn * 4];
            ulonglong2 b23 = *(const ulonglong2*)&Bs2[kk * 68 + tn * 4 + 2];
            u64 ap[2] = { pack2(av.x, av.y), pack2(av.z, av.w) };
            u64 bd[4] = { b01.x, b01.y, b23.x, b23.y };
            #pragma unroll
            for (int p = 0; p < 2; ++p)
                #pragma unroll
                for (int j = 0; j < 4; ++j)
                    fma2(acc2[p][j], ap[p], bd[j]);
        }
        __syncthreads();
    }

    #pragma unroll
    for (int j = 0; j < 4; ++j) {
        int n = n0 + tn * 4 + j;
        int gate = n >> 9, col = n & 511;
        float bb = bias[n];
        #pragma unroll
        for (int p = 0; p < 2; ++p) {
            float2 v = unpack2(acc2[p][j]);
            int mi0 = m0 + tm * 4 + p * 2;
            int t0 = mi0 >> 5, b0 = mi0 & 31;
            int t1 = (mi0 + 1) >> 5, b1 = (mi0 + 1) & 31;
            __stcs(&g_xz[(((size_t)t0 * NH + col) * NB + b0) * 4 + gate], v.x + bb);
            __stcs(&g_xz[(((size_t)t1 * NH + col) * NB + b1) * 4 + gate], v.y + bb);
        }
    }
}

// ---------------------------------------------------------------------------
// Kernel B: persistent LSTM, flag-based dataflow (no global barrier).
// 4 groups x 32 CTAs; CTA owns 16 j-cols. Warp kt consumes h rows kt*32..+31,
// produced by CTAs 2kt, 2kt+1 of the same group -> waits on 2 flags only.
// One __syncthreads per step (red ready); gates reduce red directly.
// ---------------------------------------------------------------------------
__global__ __launch_bounds__(THR_B) void lstm_kernel(
    const float* __restrict__ U, float* __restrict__ out)
{
    extern __shared__ float sm[];
    u64*   us2 = (u64*)sm;                      // [512][US2S]
    float* hs  = (float*)(us2 + NH * US2S);     // [512][8]  rows by k
    float* red = hs + NH * GB;                  // [2][16][8][REDB]

    int tid = threadIdx.x;
    int g    = blockIdx.x >> 5;                 // group 0..3
    int jblk = blockIdx.x & 31;
    int j0 = jblk * JB;

    // Load U slice as natural pairs: c = gate*16 + jj -> U[k][gate*512 + j0 + jj]
    for (int idx = tid; idx < NH * 32; idx += THR_B) {
        int k = idx >> 5, cp = idx & 31;
        int c0 = cp * 2;
        int col = (c0 >> 4) * NH + j0 + (c0 & 15);
        const float* up = &U[(size_t)k * NG + col];
        us2[k * US2S + cp] = pack2(up[0], up[1]);
    }
    __syncthreads();

    int kt = tid >> 5;                          // warp id = K slice (rows kt*32..)
    int lane = tid & 31;
    int ct = lane & 7;                          // c-tile: cols ct*8..ct*8+7
    int ks = lane >> 3;                         // inner K-split (4)
    int cp0 = ct * 4;                           // first u64 col pair (even)
    int jj = tid >> 3, bl = tid & 7;            // gates mapping (tid<128)
    float creg = 0.f;                           // cell state in register

    unsigned int* flagA = &g_flag[(g * CPG + 2 * kt) * 32];
    unsigned int* flagB = &g_flag[(g * CPG + 2 * kt + 1) * 32];
    unsigned int* myflag = &g_flag[(g * CPG + jblk) * 32];

    float4* hs4 = (float4*)hs;

    for (int t = 0; t < NT; ++t) {
        int s = t & 3;
        int p = t & 1;

        // gate threads prefetch xz (hidden under flag-wait + GEMM)
        float4 xv = make_float4(0.f, 0.f, 0.f, 0.f);
        if (tid < 128)
            xv = __ldcs((const float4*)&g_xz[(((size_t)t * NH + j0 + jj) * NB + g * GB + bl) * 4]);

        // wait for this warp's two producers to publish h[t]
        if (lane == 0) {
            while (acq_ld(flagA) < (unsigned)t) { __nanosleep(32); }
        }
        if (lane == 1) {
            while (acq_ld(flagB) < (unsigned)t) { __nanosleep(32); }
        }
        __syncwarp();

        // load this warp's 32 h rows (1 KB) from ring slot s
        {
            const float4* gh4 = (const float4*)g_h[s][g];
            int f = kt * 64 + lane * 2;
            float4 v0 = __ldcg(gh4 + f);
            float4 v1 = __ldcg(gh4 + f + 1);
            hs4[f] = v0;
            hs4[f + 1] = v1;
        }
        __syncwarp();

        // GEMM: k = kt*32 + ks*8 + i, lane tile 8b x 8c (f32x2 over c pairs)
        u64 acc2[8][4];
        #pragma unroll
        for (int b = 0; b < 8; ++b)
            #pragma unroll
            for (int c = 0; c < 4; ++c) acc2[b][c] = 0ull;

        int kb = kt * 32 + ks * 8;
        #pragma unroll
        for (int i = 0; i < 8; ++i) {
            int k = kb + i;
            float4 h01 = *(const float4*)(hs + k * 8);
            float4 h23 = *(const float4*)(hs + k * 8 + 4);
            const u64* urow = us2 + k * US2S + cp0;
            ulonglong2 ua = *(const ulonglong2*)urow;
            ulonglong2 ub = *(const ulonglong2*)(urow + 2);
            u64 up[4] = { ua.x, ua.y, ub.x, ub.y };
            u64 hp[8] = { pack2(h01.x, h01.x), pack2(h01.y, h01.y),
                          pack2(h01.z, h01.z), pack2(h01.w, h01.w),
                          pack2(h23.x, h23.x), pack2(h23.y, h23.y),
                          pack2(h23.z, h23.z), pack2(h23.w, h23.w) };
            #pragma unroll
            for (int b = 0; b < 8; ++b)
                #pragma unroll
                for (int c = 0; c < 4; ++c)
                    fma2(acc2[b][c], hp[b], up[c]);
        }

        // In-warp reduce over ks (xor 8, 16); ks==0 lanes store to red[p][kt]
        #pragma unroll
        for (int b = 0; b < 8; ++b) {
            float2 rv[4];
            #pragma unroll
            for (int c = 0; c < 4; ++c) {
                float2 v = unpack2(acc2[b][c]);
                v.x += __shfl_xor_sync(0xffffffffu, v.x, 8);
                v.y += __shfl_xor_sync(0xffffffffu, v.y, 8);
                v.x += __shfl_xor_sync(0xffffffffu, v.x, 16);
                v.y += __shfl_xor_sync(0xffffffffu, v.y, 16);
                rv[c] = v;
            }
            if (ks == 0) {
                float* dst = red + ((p * 16 + kt) * 8 + b) * REDB + ct * 8;
                *(float4*)dst       = make_float4(rv[0].x, rv[0].y, rv[1].x, rv[1].y);
                *(float4*)(dst + 4) = make_float4(rv[2].x, rv[2].y, rv[3].x, rv[3].y);
            }
        }
        __syncthreads();   // red[p] complete; all h[t] reads done

        // read-done signal for slot s (posted from a non-gate warp)
        if (tid == 128) rel_add(&g_rd[(s * GRPS + g) * 32]);

        // Gates: thread (jj 0..15, bl 0..7) reduces 16 partials x 4 gates
        if (tid < 128) {
            float zi = xv.x, zf = xv.y, zg = xv.z, zo = xv.w;
            const float* rp = red + p * (16 * 8 * REDB);
            #pragma unroll
            for (int q = 0; q < 16; ++q) {
                const float* r2 = rp + (q * 8 + bl) * REDB;
                zi += r2[jj];
                zf += r2[16 + jj];
                zg += r2[32 + jj];
                zo += r2[48 + jj];
            }

            float ig = fast_sig(zi);
            float fg = fast_sig(zf);
            float gg = fast_tanh(zg);
            float og = fast_sig(zo);

            float cn = fg * creg + ig * gg;
            creg = cn;
            float hn = og * fast_tanh(cn);

            if (t == NT - 1) {
                int bg = g * GB + bl;
                out[bg * NH + (j0 + jj)] = hn;             // hidden [B,H]
                out[NB * NH + bg * NH + (j0 + jj)] = cn;   // cell   [B,H]
            } else {
                // WAR guard: slot s2 reused from step t-3; wait till read out
                int s2 = (t + 1) & 3;
                unsigned tgt = (unsigned)CPG * ((unsigned)(t + 1) >> 2);
                if (tgt) {
                    unsigned int* rdp = &g_rd[(s2 * GRPS + g) * 32];
                    while (acq_ld(rdp) < tgt) { __nanosleep(32); }
                }
                __stcg(&g_h[s2][g][(j0 + jj) * 8 + bl], hn);
                asm volatile("bar.sync 1, 128;" ::: "memory");
                if (tid == 0) rel_add(myflag);   // publish h[t+1]
            }
        }
    }
}

// ---------------------------------------------------------------------------
extern "C" void kernel_launch(void* const* d_in, const int* in_sizes, int n_in,
                              void* d_out, int out_size) {
    const int*   tokens = (const int*)d_in[0];
    const float* emb    = (const float*)d_in[1];
    const float* W      = (const float*)d_in[2];
    const float* U      = (const float*)d_in[3];
    const float* bias   = (const float*)d_in[4];
    float* out = (float*)d_out;

    dim3 ga(NG / 64, (NB * NT) / 64);   // (32, 256)
    xz_kernel<<<ga, 256>>>(tokens, emb, W, bias);

    int smem = (int)(NH * US2S * sizeof(u64) +
                     (NH * GB + 2 * 16 * GB * REDB) * sizeof(float));
    cudaFuncSetAttribute(lstm_kernel, cudaFuncAttributeMaxDynamicSharedMemorySize, smem);
    lstm_kernel<<<NCTA_B, THR_B, smem>>>(U, out);
}

// round 10
// speedup vs baseline: 2.8091x; 2.8091x over previous
#include <cuda_runtime.h>
#include <math.h>

#define NB 32
#define NT 512
#define NE 300
#define NH 512
#define NG 2048   // 4*NH

#define NCTA_B 128
#define THR_B  512

#define HS_STRIDE 36          // floats per h row (32 used)
#define US_STRIDE 18          // u64 per U row (16 used)
#define RED_ROW   520         // floats per kt row (512 used)

// kernel A tiling
#define BM 128
#define BN 128
#define BK 20
#define NKT 15                // 300 / 20
#define AS_ROW 132            // u64 per As row (128 used)
#define BS_ROW 66             // u64 per Bs row (64 used)
#define AS_TILE (BK * AS_ROW)
#define BS_TILE (BK * BS_ROW)

typedef unsigned long long u64;

// ---------------------------------------------------------------------------
__device__ __forceinline__ u64 pack2(float lo, float hi) {
    u64 r; asm("mov.b64 %0, {%1,%2};" : "=l"(r) : "f"(lo), "f"(hi)); return r;
}
__device__ __forceinline__ void fma2(u64& d, u64 a, u64 b) {
    asm("fma.rn.f32x2 %0, %1, %2, %0;" : "+l"(d) : "l"(a), "l"(b));
}
__device__ __forceinline__ float2 unpack2(u64 v) {
    float2 f; asm("mov.b64 {%0,%1}, %2;" : "=f"(f.x), "=f"(f.y) : "l"(v)); return f;
}

__device__ __forceinline__ float fast_sig(float x) {
    float e = __expf(-x);
    return __fdividef(1.f, 1.f + e);
}
__device__ __forceinline__ float fast_tanh(float x) {
    float e = __expf(2.f * x);
    return 1.f - 2.f * __fdividef(1.f, e + 1.f);
}

__device__ __forceinline__ void bar_release_add(unsigned int* p) {
    asm volatile("red.release.gpu.global.add.u32 [%0], %1;"
                 :: "l"(p), "r"(1u) : "memory");
}
__device__ __forceinline__ unsigned int bar_acquire_ld(unsigned int* p) {
    unsigned int v;
    asm volatile("ld.acquire.gpu.global.u32 %0, [%1];"
                 : "=r"(v) : "l"(p) : "memory");
    return v;
}

// Scratch (device globals)
// xz layout: [t][j][b][gate]  (one float4 per (t,j,b))
__device__ float g_xz[(size_t)NT * NH * NB * 4];
__device__ float g_h[2][NH * NB];              // ping-pong h, [k][b]
__device__ unsigned int g_bar;

// ---------------------------------------------------------------------------
// Kernel A: z[t][n][b] = sum_k emb[tok(b,t)][k] * W[k][n] + bias[n]
// 128x128 tile, BK=20, lane tile 8x8, f32x2 (A dup pairs / B natural pairs),
// ping-pong double-buffered smem. Also zeroes g_h / g_bar.
// ---------------------------------------------------------------------------
__global__ __launch_bounds__(256, 2) void xz_kernel(
    const int* __restrict__ tokens, const float* __restrict__ emb,
    const float* __restrict__ W, const float* __restrict__ bias)
{
    extern __shared__ u64 smA[];
    u64* As2 = smA;                    // [2][BK][AS_ROW] dup pairs
    u64* Bs2 = smA + 2 * AS_TILE;      // [2][BK][BS_ROW] natural pairs
    __shared__ int toks[BM];

    int tid = threadIdx.x;
    int m0 = blockIdx.y * BM;
    int n0 = blockIdx.x * BN;

    // init duty: zero h ping-pong + barrier counter
    if (blockIdx.x == 0 && blockIdx.y < 32) {
        int i = blockIdx.y * 256 + tid;            // 0..8191 float4
        ((float4*)g_h)[i] = make_float4(0.f, 0.f, 0.f, 0.f);
        if (i == 0) g_bar = 0u;
    }

    for (int i = tid; i < BM; i += 256) {
        int m = m0 + i;                             // m = t*32 + b
        toks[i] = tokens[(m & 31) * NT + (m >> 5)];
    }
    __syncthreads();

    int tm = tid & 15, tn = tid >> 4;

    u64 acc[8][4];
    #pragma unroll
    for (int m = 0; m < 8; ++m)
        #pragma unroll
        for (int np = 0; np < 4; ++np) acc[m][np] = 0ull;

    float ra[10]; u64 rb[5];

    // ---- load tile 0 ----
    #pragma unroll
    for (int r = 0; r < 10; ++r) {
        int idx = r * 256 + tid;
        int m = idx / BK, kk = idx - m * BK;
        ra[r] = emb[(size_t)toks[m] * NE + kk];
    }
    #pragma unroll
    for (int r = 0; r < 5; ++r) {
        int idx = r * 256 + tid;
        int kk = idx >> 6, np = idx & 63;
        float2 w = *(const float2*)&W[(size_t)kk * NG + n0 + np * 2];
        rb[r] = pack2(w.x, w.y);
    }
    #pragma unroll
    for (int r = 0; r < 10; ++r) {
        int idx = r * 256 + tid;
        int m = idx / BK, kk = idx - m * BK;
        As2[kk * AS_ROW + m] = pack2(ra[r], ra[r]);
    }
    #pragma unroll
    for (int r = 0; r < 5; ++r) {
        int idx = r * 256 + tid;
        int kk = idx >> 6, np = idx & 63;
        Bs2[kk * BS_ROW + np] = rb[r];
    }
    __syncthreads();

    // ---- main loop: compute cur, load+store next ----
    for (int it = 0; it < NKT; ++it) {
        int cur = it & 1;

        if (it < NKT - 1) {
            int k0 = (it + 1) * BK;
            #pragma unroll
            for (int r = 0; r < 10; ++r) {
                int idx = r * 256 + tid;
                int m = idx / BK, kk = idx - m * BK;
                ra[r] = emb[(size_t)toks[m] * NE + k0 + kk];
            }
            #pragma unroll
            for (int r = 0; r < 5; ++r) {
                int idx = r * 256 + tid;
                int kk = idx >> 6, np = idx & 63;
                float2 w = *(const float2*)&W[(size_t)(k0 + kk) * NG + n0 + np * 2];
                rb[r] = pack2(w.x, w.y);
            }
        }

        const u64* Ab = As2 + cur * AS_TILE;
        const u64* Bb = Bs2 + cur * BS_TILE;
        #pragma unroll
        for (int kk = 0; kk < BK; ++kk) {
            const u64* arow = Ab + kk * AS_ROW + tm * 8;
            ulonglong2 a0 = *(const ulonglong2*)arow;
            ulonglong2 a1 = *(const ulonglong2*)(arow + 2);
            ulonglong2 a2 = *(const ulonglong2*)(arow + 4);
            ulonglong2 a3 = *(const ulonglong2*)(arow + 6);
            const u64* brow = Bb + kk * BS_ROW + tn * 4;
            ulonglong2 b0 = *(const ulonglong2*)brow;
            ulonglong2 b1 = *(const ulonglong2*)(brow + 2);
            u64 ad[8] = { a0.x, a0.y, a1.x, a1.y, a2.x, a2.y, a3.x, a3.y };
            u64 bp[4] = { b0.x, b0.y, b1.x, b1.y };
            #pragma unroll
            for (int m = 0; m < 8; ++m)
                #pragma unroll
                for (int np = 0; np < 4; ++np)
                    fma2(acc[m][np], ad[m], bp[np]);
        }

        if (it < NKT - 1) {
            int nb = cur ^ 1;
            u64* Aw = As2 + nb * AS_TILE;
            u64* Bw = Bs2 + nb * BS_TILE;
            #pragma unroll
            for (int r = 0; r < 10; ++r) {
                int idx = r * 256 + tid;
                int m = idx / BK, kk = idx - m * BK;
                Aw[kk * AS_ROW + m] = pack2(ra[r], ra[r]);
            }
            #pragma unroll
            for (int r = 0; r < 5; ++r) {
                int idx = r * 256 + tid;
                int kk = idx >> 6, np = idx & 63;
                Bw[kk * BS_ROW + np] = rb[r];
            }
            __syncthreads();
        }
    }

    // ---- epilogue: bias + scatter to g_xz[t][col][b][gate] ----
    #pragma unroll
    for (int np = 0; np < 4; ++np) {
        int n_a = n0 + tn * 8 + np * 2;
        int n_b = n_a + 1;
        float bb_a = bias[n_a], bb_b = bias[n_b];
        int gate_a = n_a >> 9, col_a = n_a & 511;
        int gate_b = n_b >> 9, col_b = n_b & 511;
        #pragma unroll
        for (int m = 0; m < 8; ++m) {
            float2 v = unpack2(acc[m][np]);
            int mi = m0 + tm * 8 + m;
            int t = mi >> 5, b = mi & 31;
            __stcs(&g_xz[(((size_t)t * NH + col_a) * NB + b) * 4 + gate_a], v.x + bb_a);
            __stcs(&g_xz[(((size_t)t * NH + col_b) * NB + b) * 4 + gate_b], v.y + bb_b);
        }
    }
}

// ---------------------------------------------------------------------------
// Kernel B: persistent LSTM (R5 structure — best measured). 128 CTAs x 512
// thr; CTA owns 4 h-cols across 4 gates. Warp = one kt slice (interleaved K,
// stride 16). Thread tile 4b x 4c. Chunk-pipelined h broadcast.
// ---------------------------------------------------------------------------
__global__ __launch_bounds__(THR_B) void lstm_kernel(
    const float* __restrict__ U, float* __restrict__ out)
{
    extern __shared__ float sm[];
    u64*   us2 = (u64*)sm;                      // [512][US_STRIDE] u64
    float* hs  = (float*)(us2 + NH * US_STRIDE);// [512][HS_STRIDE]
    float* red = hs + NH * HS_STRIDE;           // [16][RED_ROW]
    float* zs  = red + 16 * RED_ROW;            // [512]
    float* cs  = zs + 512;                      // [128]

    int tid = threadIdx.x;
    int cta = blockIdx.x;
    int j0 = cta * 4;

    // Load U slice as duplicated pairs: col c = gate*4+jj -> U[k][gate*512+j0+jj]
    for (int idx = tid; idx < NH * 16; idx += THR_B) {
        int k = idx >> 4, c = idx & 15;
        int col = (c >> 2) * NH + j0 + (c & 3);
        float u = U[(size_t)k * NG + col];
        us2[k * US_STRIDE + c] = pack2(u, u);
    }
    if (tid < 128) cs[tid] = 0.f;
    __syncthreads();

    // warp = kt (16 K-slices); thread tile 4 batches x 4 cols
    int kt = tid >> 5;                          // warp id
    int ot = tid & 31;
    int b0 = (ot & 7) * 4;                      // 8 b-tiles of 4
    int c0 = (ot >> 3) * 4;                     // 4 c-tiles of 4
    int jj = tid >> 5, bb = tid & 31;           // gates mapping (tid<128)

    for (int t = 0; t < NT; ++t) {
        int parity = t & 1;

        // Prefetch xz (one coalesced float4 per (j,b) thread)
        float4 xv = make_float4(0.f, 0.f, 0.f, 0.f);
        if (tid < 128)
            xv = __ldcs((const float4*)&g_xz[(((size_t)t * NH + j0 + jj) * NB + bb) * 4]);

        const float4* gh4 = (const float4*)g_h[parity];

        // ---- chunk 0 copy (rows 0..127 = 1024 float4, 2 per thread) ----
        #pragma unroll
        for (int r = 0; r < 2; ++r) {
            int f = r * 512 + tid;
            float4 v = __ldcg(gh4 + f);
            int base = f * 4;
            *(float4*)(hs + (base >> 5) * HS_STRIDE + (base & 31)) = v;
        }
        __syncthreads();

        u64 acc2[2][4];
        #pragma unroll
        for (int i = 0; i < 2; ++i)
            #pragma unroll
            for (int j = 0; j < 4; ++j) acc2[i][j] = 0ull;

        // ---- pipelined chunks: prefetch next, GEMM current ----
        #pragma unroll
        for (int c = 0; c < 4; ++c) {
            float4 pre[2];
            if (c < 3) {
                #pragma unroll
                for (int r = 0; r < 2; ++r)
                    pre[r] = __ldcg(gh4 + (c + 1) * 1024 + r * 512 + tid);
            }

            #pragma unroll
            for (int i = 0; i < 8; ++i) {
                int kk = 128 * c + 16 * i + kt;
                float4 hv = *(const float4*)(hs + kk * HS_STRIDE + b0);
                const u64* urow = us2 + kk * US_STRIDE + c0;
                ulonglong2 ua = *(const ulonglong2*)urow;
                ulonglong2 ub = *(const ulonglong2*)(urow + 2);
                u64 hp[2] = { pack2(hv.x, hv.y), pack2(hv.z, hv.w) };
                u64 up[4] = { ua.x, ua.y, ub.x, ub.y };
                #pragma unroll
                for (int p = 0; p < 2; ++p)
                    #pragma unroll
                    for (int j = 0; j < 4; ++j)
                        fma2(acc2[p][j], hp[p], up[j]);
            }

            if (c < 3) {
                #pragma unroll
                for (int r = 0; r < 2; ++r) {
                    int f = (c + 1) * 1024 + r * 512 + tid;
                    int base = f * 4;
                    *(float4*)(hs + (base >> 5) * HS_STRIDE + (base & 31)) = pre[r];
                }
                __syncthreads();
            }
        }

        // K-split partials: red[kt][c*32 + b]
        #pragma unroll
        for (int j = 0; j < 4; ++j) {
            float2 v0 = unpack2(acc2[0][j]);
            float2 v1 = unpack2(acc2[1][j]);
            *(float4*)(red + kt * RED_ROW + (c0 + j) * 32 + b0) =
                make_float4(v0.x, v0.y, v1.x, v1.y);
        }
        __syncthreads();

        // 512 outputs / 512 threads: 1 each
        {
            int o = tid;
            float s = 0.f;
            #pragma unroll
            for (int q = 0; q < 16; ++q) s += red[q * RED_ROW + o];
            zs[o] = s;
        }
        __syncthreads();

        // Gates + state update (thread = (jj, bb), 128 threads)
        if (tid < 128) {
            float zi = zs[(0 * 4 + jj) * 32 + bb] + xv.x;
            float zf = zs[(1 * 4 + jj) * 32 + bb] + xv.y;
            float zg = zs[(2 * 4 + jj) * 32 + bb] + xv.z;
            float zo = zs[(3 * 4 + jj) * 32 + bb] + xv.w;

            float ig = fast_sig(zi);
            float fg = fast_sig(zf);
            float gg = fast_tanh(zg);
            float og = fast_sig(zo);

            float cn = fg * cs[tid] + ig * gg;
            cs[tid] = cn;
            float hn = og * fast_tanh(cn);

            if (t == NT - 1) {
                out[bb * NH + (j0 + jj)] = hn;             // hidden [B,H]
                out[NB * NH + bb * NH + (j0 + jj)] = cn;   // cell   [B,H]
            } else {
                __stcg(&g_h[parity ^ 1][(j0 + jj) * NB + bb], hn);
            }
        }

        // Grid-wide barrier: release-increment, acquire-poll
        if (t < NT - 1) {
            __syncthreads();
            if (tid == 0) {
                bar_release_add(&g_bar);
                unsigned target = (unsigned)NCTA_B * (unsigned)(t + 1);
                while (bar_acquire_ld(&g_bar) < target) { }
            }
            __syncthreads();
        }
    }
}

// ---------------------------------------------------------------------------
extern "C" void kernel_launch(void* const* d_in, const int* in_sizes, int n_in,
                              void* d_out, int out_size) {
    const int*   tokens = (const int*)d_in[0];
    const float* emb    = (const float*)d_in[1];
    const float* W      = (const float*)d_in[2];
    const float* U      = (const float*)d_in[3];
    const float* bias   = (const float*)d_in[4];
    float* out = (float*)d_out;

    int smemA = (int)((2 * AS_TILE + 2 * BS_TILE) * sizeof(u64));   // 63360 B
    cudaFuncSetAttribute(xz_kernel, cudaFuncAttributeMaxDynamicSharedMemorySize, smemA);
    dim3 ga(NG / BN, (NB * NT) / BM);   // (16, 128)
    xz_kernel<<<ga, 256, smemA>>>(tokens, emb, W, bias);

    int smem = (int)(NH * US_STRIDE * sizeof(u64) +
                     (NH * HS_STRIDE + 16 * RED_ROW + 512 + 128) * sizeof(float));
    cudaFuncSetAttribute(lstm_kernel, cudaFuncAttributeMaxDynamicSharedMemorySize, smem);
    lstm_kernel<<<NCTA_B, THR_B, smem>>>(U, out);
}

// round 11
// speedup vs baseline: 3.1287x; 1.1138x over previous
#include <cuda_runtime.h>
#include <math.h>

#define NB 32
#define NT 512
#define NE 300
#define NH 512
#define NG 2048   // 4*NH

#define NCTA_B 128
#define THR_B  512

#define HS_STRIDE 36          // floats per h row (32 used)
#define US_STRIDE 18          // u64 per U row (16 used)
#define RED_ROW   520         // floats per kt row (512 used)

// kernel A tiling: 128(M) x 64(N), BK=25, lane tile 8m x 4n
#define BMA 128
#define BNA 64
#define BKA 25
#define AS_ROW 136            // floats per As row (128 used, even)
#define BS_ROW 66             // u64 per Bs row (64 used, even)

typedef unsigned long long u64;

// ---------------------------------------------------------------------------
__device__ __forceinline__ u64 pack2(float lo, float hi) {
    u64 r; asm("mov.b64 %0, {%1,%2};" : "=l"(r) : "f"(lo), "f"(hi)); return r;
}
__device__ __forceinline__ void fma2(u64& d, u64 a, u64 b) {
    asm("fma.rn.f32x2 %0, %1, %2, %0;" : "+l"(d) : "l"(a), "l"(b));
}
__device__ __forceinline__ float2 unpack2(u64 v) {
    float2 f; asm("mov.b64 {%0,%1}, %2;" : "=f"(f.x), "=f"(f.y) : "l"(v)); return f;
}

__device__ __forceinline__ float fast_sig(float x) {
    float e = __expf(-x);
    return __fdividef(1.f, 1.f + e);
}
__device__ __forceinline__ float fast_tanh(float x) {
    float e = __expf(2.f * x);              // inf-safe
    return 1.f - 2.f * __fdividef(1.f, e + 1.f);
}

__device__ __forceinline__ void bar_release_add(unsigned int* p) {
    asm volatile("red.release.gpu.global.add.u32 [%0], %1;"
                 :: "l"(p), "r"(1u) : "memory");
}
__device__ __forceinline__ unsigned int bar_acquire_ld(unsigned int* p) {
    unsigned int v;
    asm volatile("ld.acquire.gpu.global.u32 %0, [%1];"
                 : "=r"(v) : "l"(p) : "memory");
    return v;
}

// Scratch (device globals)
// xz layout: [t][j][b][gate]  (one float4 per (t,j,b))
__device__ float g_xz[(size_t)NT * NH * NB * 4];
__device__ float g_h[2][NH * NB];              // ping-pong h, [k][b]
__device__ unsigned int g_bar;

// ---------------------------------------------------------------------------
// Kernel A: z[t][n][b] = sum_k emb[tok(b,t)][k] * W[k][n] + bias[n]
// 128x64 tile, BK=25, lane tile 8m x 4n: per k, 2 A-LDS.128 (natural m-pairs,
// packed free) + 2 B-LDS.128 (dup pairs) -> 16 FFMA2. Also zeroes g_h/g_bar.
// ---------------------------------------------------------------------------
__global__ __launch_bounds__(256) void xz_kernel(
    const int* __restrict__ tokens, const float* __restrict__ emb,
    const float* __restrict__ W, const float* __restrict__ bias)
{
    __shared__ float As[BKA * AS_ROW];     // [kk][m]
    __shared__ u64   Bs2[BKA * BS_ROW];    // [kk][n] dup pairs
    __shared__ int   toks[BMA];

    int tid = threadIdx.x;
    int m0 = blockIdx.y * BMA;
    int n0 = blockIdx.x * BNA;

    // init duty: zero h ping-pong + barrier counter
    if (blockIdx.x == 0 && blockIdx.y < 32) {
        int i = blockIdx.y * 256 + tid;            // 0..8191 float4
        ((float4*)g_h)[i] = make_float4(0.f, 0.f, 0.f, 0.f);
        if (i == 0) g_bar = 0u;
    }

    for (int i = tid; i < BMA; i += 256) {
        int m = m0 + i;                             // m = t*32 + b
        toks[i] = tokens[(m & 31) * NT + (m >> 5)];
    }
    __syncthreads();

    int tm = tid & 15, tn = tid >> 4;              // 16 m-tiles x 16 n-tiles

    u64 acc[4][4];                                  // [m-pair][n]
    #pragma unroll
    for (int p = 0; p < 4; ++p)
        #pragma unroll
        for (int n = 0; n < 4; ++n) acc[p][n] = 0ull;

    for (int k0 = 0; k0 < NE; k0 += BKA) {
        // As: row-coalesced gather of emb rows (25 contiguous floats each)
        for (int idx = tid; idx < BMA * BKA; idx += 256) {
            int m = idx / BKA, kk = idx - m * BKA;
            As[kk * AS_ROW + m] = emb[(size_t)toks[m] * NE + k0 + kk];
        }
        // Bs2: coalesced W rows as dup pairs
        for (int idx = tid; idx < BKA * BNA; idx += 256) {
            int kk = idx >> 6, n = idx & 63;
            float w = W[(size_t)(k0 + kk) * NG + n0 + n];
            Bs2[kk * BS_ROW + n] = pack2(w, w);
        }
        __syncthreads();

        #pragma unroll
        for (int kk = 0; kk < BKA; ++kk) {
            const float* arow = As + kk * AS_ROW + tm * 8;
            float4 a0 = *(const float4*)arow;
            float4 a1 = *(const float4*)(arow + 4);
            const u64* brow = Bs2 + kk * BS_ROW + tn * 4;
            ulonglong2 b01 = *(const ulonglong2*)brow;
            ulonglong2 b23 = *(const ulonglong2*)(brow + 2);
            u64 hp[4] = { pack2(a0.x, a0.y), pack2(a0.z, a0.w),
                          pack2(a1.x, a1.y), pack2(a1.z, a1.w) };
            u64 bd[4] = { b01.x, b01.y, b23.x, b23.y };
            #pragma unroll
            for (int p = 0; p < 4; ++p)
                #pragma unroll
                for (int n = 0; n < 4; ++n)
                    fma2(acc[p][n], hp[p], bd[n]);
        }
        __syncthreads();
    }

    // epilogue: bias + scatter to g_xz[t][col][b][gate]
    #pragma unroll
    for (int n = 0; n < 4; ++n) {
        int ng = n0 + tn * 4 + n;
        int gate = ng >> 9, col = ng & 511;
        float bb = bias[ng];
        #pragma unroll
        for (int p = 0; p < 4; ++p) {
            float2 v = unpack2(acc[p][n]);
            int mi0 = m0 + tm * 8 + p * 2;
            int t0 = mi0 >> 5, b0 = mi0 & 31;
            int t1 = (mi0 + 1) >> 5, b1 = (mi0 + 1) & 31;
            __stcs(&g_xz[(((size_t)t0 * NH + col) * NB + b0) * 4 + gate], v.x + bb);
            __stcs(&g_xz[(((size_t)t1 * NH + col) * NB + b1) * 4 + gate], v.y + bb);
        }
    }
}

// ---------------------------------------------------------------------------
// Kernel B: persistent LSTM (R5 structure — best measured). 128 CTAs x 512
// thr; CTA owns 4 h-cols across 4 gates. Warp = one kt slice (interleaved K,
// stride 16). Thread tile 4b x 4c. Chunk-pipelined h broadcast.
// ---------------------------------------------------------------------------
__global__ __launch_bounds__(THR_B) void lstm_kernel(
    const float* __restrict__ U, float* __restrict__ out)
{
    extern __shared__ float sm[];
    u64*   us2 = (u64*)sm;                      // [512][US_STRIDE] u64
    float* hs  = (float*)(us2 + NH * US_STRIDE);// [512][HS_STRIDE]
    float* red = hs + NH * HS_STRIDE;           // [16][RED_ROW]
    float* zs  = red + 16 * RED_ROW;            // [512]
    float* cs  = zs + 512;                      // [128]

    int tid = threadIdx.x;
    int cta = blockIdx.x;
    int j0 = cta * 4;

    // Load U slice as duplicated pairs: col c = gate*4+jj -> U[k][gate*512+j0+jj]
    for (int idx = tid; idx < NH * 16; idx += THR_B) {
        int k = idx >> 4, c = idx & 15;
        int col = (c >> 2) * NH + j0 + (c & 3);
        float u = U[(size_t)k * NG + col];
        us2[k * US_STRIDE + c] = pack2(u, u);
    }
    if (tid < 128) cs[tid] = 0.f;
    __syncthreads();

    // warp = kt (16 K-slices); thread tile 4 batches x 4 cols
    int kt = tid >> 5;                          // warp id
    int ot = tid & 31;
    int b0 = (ot & 7) * 4;                      // 8 b-tiles of 4
    int c0 = (ot >> 3) * 4;                     // 4 c-tiles of 4
    int jj = tid >> 5, bb = tid & 31;           // gates mapping (tid<128)

    for (int t = 0; t < NT; ++t) {
        int parity = t & 1;

        // Prefetch xz (one coalesced float4 per (j,b) thread)
        float4 xv = make_float4(0.f, 0.f, 0.f, 0.f);
        if (tid < 128)
            xv = __ldcs((const float4*)&g_xz[(((size_t)t * NH + j0 + jj) * NB + bb) * 4]);

        const float4* gh4 = (const float4*)g_h[parity];

        // ---- chunk 0 copy (rows 0..127 = 1024 float4, 2 per thread) ----
        #pragma unroll
        for (int r = 0; r < 2; ++r) {
            int f = r * 512 + tid;
            float4 v = __ldcg(gh4 + f);
            int base = f * 4;
            *(float4*)(hs + (base >> 5) * HS_STRIDE + (base & 31)) = v;
        }
        __syncthreads();

        u64 acc2[2][4];
        #pragma unroll
        for (int i = 0; i < 2; ++i)
            #pragma unroll
            for (int j = 0; j < 4; ++j) acc2[i][j] = 0ull;

        // ---- pipelined chunks: prefetch next, GEMM current ----
        #pragma unroll
        for (int c = 0; c < 4; ++c) {
            float4 pre[2];
            if (c < 3) {
                #pragma unroll
                for (int r = 0; r < 2; ++r)
                    pre[r] = __ldcg(gh4 + (c + 1) * 1024 + r * 512 + tid);
            }

            #pragma unroll
            for (int i = 0; i < 8; ++i) {
                int kk = 128 * c + 16 * i + kt;
                float4 hv = *(const float4*)(hs + kk * HS_STRIDE + b0);
                const u64* urow = us2 + kk * US_STRIDE + c0;
                ulonglong2 ua = *(const ulonglong2*)urow;
                ulonglong2 ub = *(const ulonglong2*)(urow + 2);
                u64 hp[2] = { pack2(hv.x, hv.y), pack2(hv.z, hv.w) };
                u64 up[4] = { ua.x, ua.y, ub.x, ub.y };
                #pragma unroll
                for (int p = 0; p < 2; ++p)
                    #pragma unroll
                    for (int j = 0; j < 4; ++j)
                        fma2(acc2[p][j], hp[p], up[j]);
            }

            if (c < 3) {
                #pragma unroll
                for (int r = 0; r < 2; ++r) {
                    int f = (c + 1) * 1024 + r * 512 + tid;
                    int base = f * 4;
                    *(float4*)(hs + (base >> 5) * HS_STRIDE + (base & 31)) = pre[r];
                }
                __syncthreads();
            }
        }

        // K-split partials: red[kt][c*32 + b]
        #pragma unroll
        for (int j = 0; j < 4; ++j) {
            float2 v0 = unpack2(acc2[0][j]);
            float2 v1 = unpack2(acc2[1][j]);
            *(float4*)(red + kt * RED_ROW + (c0 + j) * 32 + b0) =
                make_float4(v0.x, v0.y, v1.x, v1.y);
        }
        __syncthreads();

        // 512 outputs / 512 threads: 1 each
        {
            int o = tid;
            float s = 0.f;
            #pragma unroll
            for (int q = 0; q < 16; ++q) s += red[q * RED_ROW + o];
            zs[o] = s;
        }
        __syncthreads();

        // Gates + state update (thread = (jj, bb), 128 threads)
        if (tid < 128) {
            float zi = zs[(0 * 4 + jj) * 32 + bb] + xv.x;
            float zf = zs[(1 * 4 + jj) * 32 + bb] + xv.y;
            float zg = zs[(2 * 4 + jj) * 32 + bb] + xv.z;
            float zo = zs[(3 * 4 + jj) * 32 + bb] + xv.w;

            float ig = fast_sig(zi);
            float fg = fast_sig(zf);
            float gg = fast_tanh(zg);
            float og = fast_sig(zo);

            float cn = fg * cs[tid] + ig * gg;
            cs[tid] = cn;
            float hn = og * fast_tanh(cn);

            if (t == NT - 1) {
                out[bb * NH + (j0 + jj)] = hn;             // hidden [B,H]
                out[NB * NH + bb * NH + (j0 + jj)] = cn;   // cell   [B,H]
            } else {
                __stcg(&g_h[parity ^ 1][(j0 + jj) * NB + bb], hn);
            }
        }

        // Grid-wide barrier: release-increment, acquire-poll
        if (t < NT - 1) {
            __syncthreads();
            if (tid == 0) {
                bar_release_add(&g_bar);
                unsigned target = (unsigned)NCTA_B * (unsigned)(t + 1);
                while (bar_acquire_ld(&g_bar) < target) { }
            }
            __syncthreads();
        }
    }
}

// ---------------------------------------------------------------------------
extern "C" void kernel_launch(void* const* d_in, const int* in_sizes, int n_in,
                              void* d_out, int out_size) {
    const int*   tokens = (const int*)d_in[0];
    const float* emb    = (const float*)d_in[1];
    const float* W      = (const float*)d_in[2];
    const float* U      = (const float*)d_in[3];
    const float* bias   = (const float*)d_in[4];
    float* out = (float*)d_out;

    dim3 ga(NG / BNA, (NB * NT) / BMA);   // (32, 128)
    xz_kernel<<<ga, 256>>>(tokens, emb, W, bias);

    int smem = (int)(NH * US_STRIDE * sizeof(u64) +
                     (NH * HS_STRIDE + 16 * RED_ROW + 512 + 128) * sizeof(float));
    cudaFuncSetAttribute(lstm_kernel, cudaFuncAttributeMaxDynamicSharedMemorySize, smem);
    lstm_kernel<<<NCTA_B, THR_B, smem>>>(U, out);
}